// round 12
// baseline (speedup 1.0000x reference)
#include <cuda_runtime.h>
#include <cstdint>
#include <cstddef>

// Problem constants (fixed by the dataset)
#define B_  32
#define N_  1024
#define D_  128
#define C_  16
// P*P = 16, Hg = 32, out image 128x128 per (b,c)

// Mapping: CTA = 256 threads = 8 warps, 64 token rows per CTA (8 rows/warp).
// Lane l: row = (warp<<3) + (l>>2), pr = l&3 (thread owns patch row pr:
// p = 4*pr .. 4*pr+3). Grid = 512 CTAs -> ~3.5 CTAs/SM, ~27 warps/SM.
#define THREADS 256
#define NROWS   64

// Shared layout (floats), static (<48KB)
//   sx  [64][128]   x tile, XOR-swizzled 16B chunks        (32KB)
//   swt [32][68]    W transposed: per-d4 272B blocks,
//                   bank-swizzled pr sub-blocks            (8.5KB)
//   scbm[256] + smask[16]
#define SWT_FLOATS  (32 * 68)
#define SX_FLOATS   (NROWS * D_)

// Precomputed channel table: cb[c*16+p] = emb[c]·W[p] + bias[p]
__device__ float g_cb[C_ * 16];

__device__ __forceinline__ uint32_t smem_u32(const void* p) {
    return (uint32_t)__cvta_generic_to_shared(p);
}

// Blackwell packed fp32x2 FMA (PTX-only)
#define FMA_F32X2(d, a, b, c) \
    asm("fma.rn.f32x2 %0, %1, %2, %3;" : "=l"(d) : "l"(a), "l"(b), "l"(c))

// W^T float offset for (p, d4): block d4 (68 floats = 272B), pr sub-block
// swizzled so simultaneous pr=0..3 accesses hit banks {0,16,4,20}.
__device__ __forceinline__ int swt_off(int p, int d4) {
    int pr = p >> 2, pc = p & 3;
    return d4 * 68 + pr * 16 + ((pr >> 1) & 1) * 4 + pc * 4;
}

// ---------------------------------------------------------------------------
// Kernel A: build the 16x16 channel table once (one warp per entry).
// ---------------------------------------------------------------------------
__global__ void __launch_bounds__(1024, 1)
cb_table_kernel(const float* __restrict__ emb,   // [256, D]
                const float* __restrict__ W,     // [16, D]
                const float* __restrict__ bias)  // [16]
{
    const int w = (blockIdx.x * blockDim.x + threadIdx.x) >> 5;  // 0..255
    const int l = threadIdx.x & 31;
    const int c = w >> 4, p = w & 15;

    float4 e = *reinterpret_cast<const float4*>(emb + (size_t)c * D_ + l * 4);
    float4 v = *reinterpret_cast<const float4*>(W   + (size_t)p * D_ + l * 4);
    float s = e.x * v.x + e.y * v.y + e.z * v.z + e.w * v.w;
    #pragma unroll
    for (int off = 16; off > 0; off >>= 1)
        s += __shfl_xor_sync(0xffffffffu, s, off);
    if (l == 0) g_cb[w] = s + bias[p];
}

// ---------------------------------------------------------------------------
// Kernel B: main fused decode.
// ---------------------------------------------------------------------------
__global__ void __launch_bounds__(THREADS, 4)
QBD_main_kernel(
    const float* __restrict__ x,     // [B, N, D]
    const float* __restrict__ pmask, // [B, C]
    const float* __restrict__ W,     // [16, D]
    float* __restrict__ out)         // [B, C, 128, 128]
{
    __shared__ float sx[SX_FLOATS];
    __shared__ float swt[SWT_FLOATS];
    __shared__ float scbm[256];
    __shared__ float smask[16];

    const int t   = threadIdx.x;
    const int bid = blockIdx.x;

    // ---- Stage x tile (64 rows x 128 floats = 32KB contiguous) via cp.async,
    //      XOR-swizzled: phys 16B-chunk col = c ^ (row & 7) ----
    const float4* gx = reinterpret_cast<const float4*>(x + (size_t)bid * NROWS * D_);
    #pragma unroll
    for (int i = 0; i < 8; ++i) {
        int k = t + THREADS * i;                 // 0..2047: row = k>>5, col16 = k&31
        int row = k >> 5, col = k & 31;
        uint32_t dst = smem_u32(sx + row * D_ + ((col ^ (row & 7)) << 2));
        asm volatile("cp.async.cg.shared.global [%0], [%1], 16;\n"
                     :: "r"(dst), "l"(gx + k));
    }
    asm volatile("cp.async.commit_group;\n");

    // ---- Meanwhile: load W (L2-hot, 8KB) and store TRANSPOSED+swizzled;
    //      also build mask-premultiplied channel table ----
    const float4* gw = reinterpret_cast<const float4*>(W);   // [16][32] float4
    #pragma unroll
    for (int i = 0; i < 2; ++i) {
        int idx = t + THREADS * i;               // 0..511: p = idx>>5, d4 = idx&31
        int p = idx >> 5, d4 = idx & 31;
        float4 w4 = gw[idx];
        *reinterpret_cast<float4*>(swt + swt_off(p, d4)) = w4;
    }
    {
        int b0 = (bid * NROWS) >> 10;            // batch of this CTA (64 | 1024 -> unique)
        scbm[t] = g_cb[t] * pmask[b0 * C_ + (t >> 4)];
        if (t < C_) smask[t] = pmask[b0 * C_ + t];
    }

    asm volatile("cp.async.wait_group 0;\n");
    __syncthreads();

    // ---- Main dot products. Lane: row = w*8 + (l>>2), pr = l&3.
    //      xv: 8 distinct swizzled 16B (banks 4*((d4^xs)&7)) + 4-lane
    //          broadcast -> 1 phase.
    //      wv: 4 distinct 16B at banks {0,16,4,20}(+shift) -> 1 phase each. ----
    const int l   = t & 31;
    const int row = ((t >> 5) << 3) + (l >> 2);  // 0..63
    const int pr  = l & 3;
    const int xs  = row & 7;
    const float* xr = sx + row * D_;
    const float* wbase = swt + pr * 16 + ((pr >> 1) & 1) * 4;

    unsigned long long acc2[4] = {0ull, 0ull, 0ull, 0ull};   // pc = 0..3

    #pragma unroll
    for (int d4 = 0; d4 < 32; ++d4) {
        ulonglong2 xv = *reinterpret_cast<const ulonglong2*>(xr + ((d4 ^ xs) << 2));
        const float* wd = wbase + d4 * 68;
        #pragma unroll
        for (int pc = 0; pc < 4; ++pc) {
            ulonglong2 wv = *reinterpret_cast<const ulonglong2*>(wd + pc * 4);
            FMA_F32X2(acc2[pc], xv.x, wv.x, acc2[pc]);
            FMA_F32X2(acc2[pc], xv.y, wv.y, acc2[pc]);
        }
    }

    // ---- Horizontal add (even+odd d); pack pairs: thread now holds
    //      xa[4*pr + 0..3] = one full patch row -> STG.128 epilogue ----
    float xa[4];
    #pragma unroll
    for (int pc = 0; pc < 4; ++pc) {
        uint32_t lo, hi;
        asm("mov.b64 {%0, %1}, %2;" : "=r"(lo), "=r"(hi) : "l"(acc2[pc]));
        xa[pc] = __uint_as_float(lo) + __uint_as_float(hi);
    }
    unsigned long long xa2[2];
    #pragma unroll
    for (int k = 0; k < 2; ++k)
        asm("mov.b64 %0, {%1, %2};" : "=l"(xa2[k])
            : "r"(__float_as_uint(xa[2 * k])), "r"(__float_as_uint(xa[2 * k + 1])));

    // ---- Epilogue: out[b][c][hg*4+pr][wg*4 + 0..3] = xa*m + cbm.
    //      Per (warp,c): 8 rows x 4 pr -> 4 contiguous 128B lines, 1 STG.128. ----
    const int n  = bid * NROWS + row;
    const int b  = n >> 10;
    const int nn = n & 1023;
    const int hg = nn >> 5, wg = nn & 31;
    float* ob = out + (size_t)b * (C_ * 128 * 128) + (hg * 4 + pr) * 128 + wg * 4;

    #pragma unroll
    for (int c = 0; c < C_; ++c) {
        float m = smask[c];
        unsigned long long m2;
        asm("mov.b64 %0, {%1, %1};" : "=l"(m2) : "r"(__float_as_uint(m)));
        ulonglong2 cb = *reinterpret_cast<const ulonglong2*>(scbm + c * 16 + pr * 4);
        ulonglong2 v;
        FMA_F32X2(v.x, xa2[0], m2, cb.x);
        FMA_F32X2(v.y, xa2[1], m2, cb.y);
        *reinterpret_cast<ulonglong2*>(ob + c * (128 * 128)) = v;
    }
}

extern "C" void kernel_launch(void* const* d_in, const int* in_sizes, int n_in,
                              void* d_out, int out_size)
{
    const float* x    = (const float*)d_in[0];  // [32,1024,128]
    const float* pm   = (const float*)d_in[1];  // [32,16]
    const float* emb  = (const float*)d_in[2];  // [256,128]
    const float* W    = (const float*)d_in[3];  // [16,128]
    const float* bias = (const float*)d_in[4];  // [16]
    float* out        = (float*)d_out;          // [32,16,128,128]

    // Kernel A: 256-entry channel table (one warp per entry)
    cb_table_kernel<<<8, 1024>>>(emb, W, bias);

    // Kernel B: 512 CTAs x 256 threads, 64 rows each
    QBD_main_kernel<<<B_ * N_ / NROWS, THREADS>>>(x, pm, W, out);
}

// round 14
// speedup vs baseline: 1.0056x; 1.0056x over previous
#include <cuda_runtime.h>
#include <cstdint>
#include <cstddef>

// Problem constants (fixed by the dataset)
#define B_  32
#define N_  1024
#define D_  128
#define C_  16
// P*P = 16, Hg = 32, out image 128x128 per (b,c)

// Mapping: CTA = 256 threads = 8 warps, 64 token rows per CTA (8 rows/warp).
// Lane l: row = (warp<<3) + (l>>2), pr = l&3 (thread owns patch row pr:
// p = 4*pr .. 4*pr+3). Grid = 512 CTAs -> ~3.5 CTAs/SM, ~27 warps/SM.
#define THREADS 256
#define NROWS   64

// Shared layout (floats), static (<48KB)
//   sx  [64][128]   x tile, XOR-swizzled 16B chunks        (32KB)
//   swt [32][68]    W transposed: per-d4 272B blocks,
//                   bank-swizzled pr sub-blocks            (8.5KB)
//   scbm[256] + smask[16]
#define SWT_FLOATS  (32 * 68)
#define SX_FLOATS   (NROWS * D_)

// Precomputed channel table: cb[c*16+p] = emb[c]·W[p] + bias[p]
__device__ float g_cb[C_ * 16];

__device__ __forceinline__ uint32_t smem_u32(const void* p) {
    return (uint32_t)__cvta_generic_to_shared(p);
}

// Blackwell packed fp32x2 FMA (PTX-only)
#define FMA_F32X2(d, a, b, c) \
    asm("fma.rn.f32x2 %0, %1, %2, %3;" : "=l"(d) : "l"(a), "l"(b), "l"(c))

// W^T float offset for (p, d4): block d4 (68 floats = 272B), pr sub-block
// swizzled so simultaneous pr=0..3 accesses hit banks {0,16,4,20}.
__device__ __forceinline__ int swt_off(int p, int d4) {
    int pr = p >> 2, pc = p & 3;
    return d4 * 68 + pr * 16 + ((pr >> 1) & 1) * 4 + pc * 4;
}

// ---------------------------------------------------------------------------
// Kernel A: build the 16x16 channel table once (one warp per entry).
// ---------------------------------------------------------------------------
__global__ void __launch_bounds__(1024, 1)
cb_table_kernel(const float* __restrict__ emb,   // [256, D]
                const float* __restrict__ W,     // [16, D]
                const float* __restrict__ bias)  // [16]
{
    const int w = (blockIdx.x * blockDim.x + threadIdx.x) >> 5;  // 0..255
    const int l = threadIdx.x & 31;
    const int c = w >> 4, p = w & 15;

    float4 e = *reinterpret_cast<const float4*>(emb + (size_t)c * D_ + l * 4);
    float4 v = *reinterpret_cast<const float4*>(W   + (size_t)p * D_ + l * 4);
    float s = e.x * v.x + e.y * v.y + e.z * v.z + e.w * v.w;
    #pragma unroll
    for (int off = 16; off > 0; off >>= 1)
        s += __shfl_xor_sync(0xffffffffu, s, off);
    if (l == 0) g_cb[w] = s + bias[p];
}

// ---------------------------------------------------------------------------
// Kernel B: main fused decode.
// ---------------------------------------------------------------------------
__global__ void __launch_bounds__(THREADS, 4)
QBD_main_kernel(
    const float* __restrict__ x,     // [B, N, D]
    const float* __restrict__ pmask, // [B, C]
    const float* __restrict__ W,     // [16, D]
    float* __restrict__ out)         // [B, C, 128, 128]
{
    __shared__ float sx[SX_FLOATS];
    __shared__ float swt[SWT_FLOATS];
    __shared__ float scbm[256];
    __shared__ float smask[16];

    const int t   = threadIdx.x;
    const int bid = blockIdx.x;

    // ---- Stage x tile (64 rows x 128 floats = 32KB contiguous) via cp.async,
    //      XOR-swizzled: phys 16B-chunk col = c ^ (row & 7) ----
    const float4* gx = reinterpret_cast<const float4*>(x + (size_t)bid * NROWS * D_);
    #pragma unroll
    for (int i = 0; i < 8; ++i) {
        int k = t + THREADS * i;                 // 0..2047: row = k>>5, col16 = k&31
        int row = k >> 5, col = k & 31;
        uint32_t dst = smem_u32(sx + row * D_ + ((col ^ (row & 7)) << 2));
        asm volatile("cp.async.cg.shared.global [%0], [%1], 16;\n"
                     :: "r"(dst), "l"(gx + k));
    }
    asm volatile("cp.async.commit_group;\n");

    // ---- Meanwhile: load W (L2-hot, 8KB) and store TRANSPOSED+swizzled;
    //      also build mask-premultiplied channel table ----
    const float4* gw = reinterpret_cast<const float4*>(W);   // [16][32] float4
    #pragma unroll
    for (int i = 0; i < 2; ++i) {
        int idx = t + THREADS * i;               // 0..511: p = idx>>5, d4 = idx&31
        int p = idx >> 5, d4 = idx & 31;
        float4 w4 = gw[idx];
        *reinterpret_cast<float4*>(swt + swt_off(p, d4)) = w4;
    }
    {
        int b0 = (bid * NROWS) >> 10;            // batch of this CTA (64 | 1024 -> unique)
        scbm[t] = g_cb[t] * pmask[b0 * C_ + (t >> 4)];
        if (t < C_) smask[t] = pmask[b0 * C_ + t];
    }

    asm volatile("cp.async.wait_group 0;\n");
    __syncthreads();

    // ---- Main dot products. Lane: row = w*8 + (l>>2), pr = l&3.
    //      xv: 8 distinct swizzled 16B (banks 4*((d4^xs)&7)) + 4-lane
    //          broadcast -> 1 phase.
    //      wv: 4 distinct 16B at banks {0,16,4,20}(+shift) -> 1 phase each. ----
    const int l   = t & 31;
    const int row = ((t >> 5) << 3) + (l >> 2);  // 0..63
    const int pr  = l & 3;
    const int xs  = row & 7;
    const float* xr = sx + row * D_;
    const float* wbase = swt + pr * 16 + ((pr >> 1) & 1) * 4;

    unsigned long long acc2[4] = {0ull, 0ull, 0ull, 0ull};   // pc = 0..3

    #pragma unroll
    for (int d4 = 0; d4 < 32; ++d4) {
        ulonglong2 xv = *reinterpret_cast<const ulonglong2*>(xr + ((d4 ^ xs) << 2));
        const float* wd = wbase + d4 * 68;
        #pragma unroll
        for (int pc = 0; pc < 4; ++pc) {
            ulonglong2 wv = *reinterpret_cast<const ulonglong2*>(wd + pc * 4);
            FMA_F32X2(acc2[pc], xv.x, wv.x, acc2[pc]);
            FMA_F32X2(acc2[pc], xv.y, wv.y, acc2[pc]);
        }
    }

    // ---- Horizontal add (even+odd d); pack pairs: thread now holds
    //      xa[4*pr + 0..3] = one full patch row -> STG.128 epilogue ----
    float xa[4];
    #pragma unroll
    for (int pc = 0; pc < 4; ++pc) {
        uint32_t lo, hi;
        asm("mov.b64 {%0, %1}, %2;" : "=r"(lo), "=r"(hi) : "l"(acc2[pc]));
        xa[pc] = __uint_as_float(lo) + __uint_as_float(hi);
    }
    unsigned long long xa2[2];
    #pragma unroll
    for (int k = 0; k < 2; ++k)
        asm("mov.b64 %0, {%1, %2};" : "=l"(xa2[k])
            : "r"(__float_as_uint(xa[2 * k])), "r"(__float_as_uint(xa[2 * k + 1])));

    // ---- Epilogue: out[b][c][hg*4+pr][wg*4 + 0..3] = xa*m + cbm.
    //      Per (warp,c): 8 rows x 4 pr -> 4 contiguous 128B lines, 1 STG.128. ----
    const int n  = bid * NROWS + row;
    const int b  = n >> 10;
    const int nn = n & 1023;
    const int hg = nn >> 5, wg = nn & 31;
    float* ob = out + (size_t)b * (C_ * 128 * 128) + (hg * 4 + pr) * 128 + wg * 4;

    #pragma unroll
    for (int c = 0; c < C_; ++c) {
        float m = smask[c];
        unsigned long long m2;
        asm("mov.b64 %0, {%1, %1};" : "=l"(m2) : "r"(__float_as_uint(m)));
        ulonglong2 cb = *reinterpret_cast<const ulonglong2*>(scbm + c * 16 + pr * 4);
        ulonglong2 v;
        FMA_F32X2(v.x, xa2[0], m2, cb.x);
        FMA_F32X2(v.y, xa2[1], m2, cb.y);
        *reinterpret_cast<ulonglong2*>(ob + c * (128 * 128)) = v;
    }
}

extern "C" void kernel_launch(void* const* d_in, const int* in_sizes, int n_in,
                              void* d_out, int out_size)
{
    const float* x    = (const float*)d_in[0];  // [32,1024,128]
    const float* pm   = (const float*)d_in[1];  // [32,16]
    const float* emb  = (const float*)d_in[2];  // [256,128]
    const float* W    = (const float*)d_in[3];  // [16,128]
    const float* bias = (const float*)d_in[4];  // [16]
    float* out        = (float*)d_out;          // [32,16,128,128]

    // Kernel A: 256-entry channel table (one warp per entry)
    cb_table_kernel<<<8, 1024>>>(emb, W, bias);

    // Kernel B: 512 CTAs x 256 threads, 64 rows each
    QBD_main_kernel<<<B_ * N_ / NROWS, THREADS>>>(x, pm, W, out);
}